// round 5
// baseline (speedup 1.0000x reference)
#include <cuda_runtime.h>

// Problem constants (fixed by the dataset)
#define B_TOTAL   131072
#define S_DIM     17
#define A_DIM     7
#define DPHI      128
#define DPSI      8

#define NPROD     64                  // producer blocks: 32 i-chunks x 2 j-halves
#define I_PER     4                   // i-values per chunk
#define TILE      128                 // samples per consumer block
#define NCONS     (B_TOTAL / TILE)    // 1024 consumer blocks
#define CPS       136                 // padded [17][8] floats per partial
#define CPS4      34                  // ... as float4

// Scratch (zero-initialized at module load; pad columns are never written,
// so they remain 0 across all replays).
__device__ float    g_Cpart[NPROD * CPS];
__device__ float    g_C[CPS];
__device__ unsigned g_prod_count = 0;
__device__ unsigned g_flag       = 0;
__device__ unsigned g_done       = 0;

__device__ __forceinline__ unsigned ld_acquire(const unsigned* p) {
    unsigned v;
    asm volatile("ld.global.acquire.gpu.u32 %0, [%1];" : "=r"(v) : "l"(p) : "memory");
    return v;
}
__device__ __forceinline__ void st_release(unsigned* p, unsigned v) {
    asm volatile("st.global.release.gpu.u32 [%0], %1;" :: "l"(p), "r"(v) : "memory");
}

// ---------------------------------------------------------------------------
// Single fused kernel.
//   Blocks [0, NPROD):           producers — partial C over (i-chunk, j-half)
//   Blocks [NPROD, NPROD+NCONS): consumers — out[b] = state[b]^T C action[b]
// Deadlock-free: consumer smem (12832 B) + 128 thr => 16 CTAs/SM resident,
// 148 SMs * 16 = 2368 slots > 1088 total CTAs, so producers (lowest blockIdx,
// wave 1) are always co-resident with every spinning consumer.
// ---------------------------------------------------------------------------
__global__ __launch_bounds__(128)
void koopman_fused(const float* __restrict__ state,    // [B,17]
                   const float* __restrict__ action,   // [B,7]
                   const float* __restrict__ Wphi,     // [128,17]
                   const float* __restrict__ Wpsi,     // [8,7]
                   const float* __restrict__ K,        // [128,128,8]
                   const float* __restrict__ wlin,     // [1,128]
                   float* __restrict__ out)            // [B]
{
    // One buffer, carved per role.
    // consumer: Ss = [0,2176) , As = [2176,3072) , Csm = [3072,3208)
    // producer: Msm = [0,512)
    __shared__ __align__(16) float sbuf[3208];
    const int tid = threadIdx.x;

    if (blockIdx.x < NPROD) {
        // =================== PRODUCER ===================
        const int p     = blockIdx.x;
        const int chunk = p >> 1;          // i-chunk (0..31)
        const int half  = p & 1;           // j-half  (0..1)
        float* Msm = sbuf;                 // 512 floats: M[j_local][z]

        // M[j_local, z] = sum_{i in chunk} w[i] * K[i, j0+j_local, z]
        {
            const float4* K4 = reinterpret_cast<const float4*>(K);
            float4 acc = make_float4(0.f, 0.f, 0.f, 0.f);
#pragma unroll
            for (int ii = 0; ii < I_PER; ii++) {
                const int i = chunk * I_PER + ii;
                const float w = __ldg(&wlin[i]);
                const float4 kv = K4[i * 256 + half * 128 + tid];
                acc.x = fmaf(w, kv.x, acc.x);
                acc.y = fmaf(w, kv.y, acc.y);
                acc.z = fmaf(w, kv.z, acc.z);
                acc.w = fmaf(w, kv.w, acc.w);
            }
            reinterpret_cast<float4*>(Msm)[tid] = acc;
        }
        __syncthreads();

        // C_p[s,a] = sum_{j in half, z} M[j,z] * Wphi[j,s] * Wpsi[z,a]
        if (tid < S_DIM * A_DIM) {         // 119 threads, 1 per (s,a)
            const int s = tid / A_DIM;
            const int a = tid - s * A_DIM;

            float psi[DPSI];
#pragma unroll
            for (int z = 0; z < DPSI; z++) psi[z] = __ldg(&Wpsi[z * A_DIM + a]);

            const int j0 = half * 64;
            float c0 = 0.f, c1 = 0.f;      // 2 accumulators to shorten chain
#pragma unroll 4
            for (int jl = 0; jl < 64; jl += 2) {
                float in0 = 0.f, in1 = 0.f;
#pragma unroll
                for (int z = 0; z < DPSI; z++) {
                    in0 = fmaf(Msm[jl * DPSI + z],       psi[z], in0);
                    in1 = fmaf(Msm[(jl + 1) * DPSI + z], psi[z], in1);
                }
                c0 = fmaf(__ldg(&Wphi[(j0 + jl)     * S_DIM + s]), in0, c0);
                c1 = fmaf(__ldg(&Wphi[(j0 + jl + 1) * S_DIM + s]), in1, c1);
            }
            g_Cpart[p * CPS + s * 8 + a] = c0 + c1;   // pads never touched
        }
        __threadfence();                   // publish partials (gpu scope)
        __syncthreads();

        __shared__ bool isLast;
        if (tid == 0)
            isLast = (atomicAdd(&g_prod_count, 1u) == NPROD - 1);
        __syncthreads();

        if (isLast) {
            __threadfence();               // acquire all partials
            if (tid < CPS4) {              // reduce 64 partials, fixed order
                const float4* P4 = reinterpret_cast<const float4*>(g_Cpart);
                float4 v = make_float4(0.f, 0.f, 0.f, 0.f);
#pragma unroll 8
                for (int q = 0; q < NPROD; q++) {
                    const float4 x = P4[q * CPS4 + tid];
                    v.x += x.x; v.y += x.y; v.z += x.z; v.w += x.w;
                }
                reinterpret_cast<float4*>(g_C)[tid] = v;
                __threadfence();
            }
            __syncthreads();
            if (tid == 0) st_release(&g_flag, 1u);
        }
        return;
    }

    // =================== CONSUMER ===================
    const int bx = blockIdx.x - NPROD;     // tile index 0..1023
    float* Ss  = sbuf;                     // [128][17]
    float* As  = sbuf + TILE * S_DIM;      // [128][7]
    float* Csm = sbuf + TILE * (S_DIM + A_DIM);  // padded [17][8]

    // --- issue ALL staging loads up front (7 x LDG.128, MLP = 7), storing
    //     each to smem as it lands so the LSU can retire in order ---
    {
        const float4* S4 = reinterpret_cast<const float4*>(state)  + (size_t)bx * 544;
        const float4* A4 = reinterpret_cast<const float4*>(action) + (size_t)bx * 224;
        float4* D = reinterpret_cast<float4*>(Ss);
        float4* E = reinterpret_cast<float4*>(As);
        D[tid]       = S4[tid];
        D[tid + 128] = S4[tid + 128];
        D[tid + 256] = S4[tid + 256];
        D[tid + 384] = S4[tid + 384];
        if (tid < 32) D[tid + 512] = S4[tid + 512];
        E[tid] = A4[tid];
        if (tid < 96) E[tid + 128] = A4[tid + 128];
    }

    // --- wait for C (overlaps with the load latency above) ---
    if (tid == 0) {
        while (ld_acquire(&g_flag) == 0u) __nanosleep(64);
    }
    __syncthreads();

    if (tid < CPS4)
        reinterpret_cast<float4*>(Csm)[tid] =
            reinterpret_cast<const float4*>(g_C)[tid];
    __syncthreads();

    // --- per-sample bilinear form ---
    const float* av = As + tid * A_DIM;    // lane stride 7: conflict-free
    const float v0 = av[0], v1 = av[1], v2 = av[2], v3 = av[3];
    const float v4 = av[4], v5 = av[5], v6 = av[6];

    const float4* C4 = reinterpret_cast<const float4*>(Csm);
    const float*  st = Ss + tid * S_DIM;   // lane stride 17: conflict-free

    float r = 0.f;
#pragma unroll
    for (int s = 0; s < S_DIM; s++) {
        const float4 c0 = C4[2 * s];       // broadcast LDS.128
        const float4 c1 = C4[2 * s + 1];
        float t;
        t = c0.x * v0;
        t = fmaf(c0.y, v1, t);
        t = fmaf(c0.z, v2, t);
        t = fmaf(c0.w, v3, t);
        t = fmaf(c1.x, v4, t);
        t = fmaf(c1.y, v5, t);
        t = fmaf(c1.z, v6, t);
        r = fmaf(st[s], t, r);
    }
    out[bx * TILE + tid] = r;

    // --- last consumer resets counters for the next graph replay ---
    __syncthreads();
    if (tid == 0) {
        if (atomicAdd(&g_done, 1u) == NCONS - 1) {
            g_prod_count = 0;
            g_flag       = 0;
            g_done       = 0;
        }
    }
}

// ---------------------------------------------------------------------------
extern "C" void kernel_launch(void* const* d_in, const int* in_sizes, int n_in,
                              void* d_out, int out_size)
{
    const float* state  = (const float*)d_in[0];
    const float* action = (const float*)d_in[1];
    const float* Wphi   = (const float*)d_in[2];
    const float* Wpsi   = (const float*)d_in[3];
    const float* K      = (const float*)d_in[4];
    const float* wlin   = (const float*)d_in[5];
    float* out = (float*)d_out;

    koopman_fused<<<NPROD + NCONS, 128>>>(state, action, Wphi, Wpsi, K, wlin, out);
}

// round 6
// speedup vs baseline: 1.2315x; 1.2315x over previous
#include <cuda_runtime.h>

// Problem constants (fixed by the dataset)
#define B_TOTAL   131072
#define S_DIM     17
#define A_DIM     7
#define DPHI      128
#define DPSI      8

#define NPART     32                  // blocks in the precompute kernel
#define I_PER     (DPHI / NPART)      // 4 i-values per block
#define CPS       136                 // padded [17][8] floats per partial
#define CPS4      34                  // ... as float4

#define TILE      256                 // samples per k_main block
#define NBLK_MAIN (B_TOTAL / TILE)    // 512 blocks

// Per-block partial C matrices, padded [17][8] (pad col written as 0).
__device__ float g_Cpart[NPART * CPS];

// ---------------------------------------------------------------------------
// Kernel 1 (fence-free, R1-proven): block p computes the partial C over
// i in [p*I_PER, (p+1)*I_PER):
//   M_p[j,z] = sum_{i in chunk} w_lin[i] * K[i,j,z]
//   C_p[s,a] = sum_{j,z} M_p[j,z] * W_phi[j,s] * W_psi[z,a]
// ---------------------------------------------------------------------------
__global__ __launch_bounds__(256)
void k_partialC(const float* __restrict__ Wphi,   // [128,17]
                const float* __restrict__ Wpsi,   // [8,7]
                const float* __restrict__ K,      // [128,128,8]
                const float* __restrict__ wlin)   // [1,128]
{
    __shared__ float Msm[DPHI * DPSI];   // 1024 floats, layout j*8+z
    __shared__ float Ctmp[256];

    const int p   = blockIdx.x;
    const int tid = threadIdx.x;         // 256 threads

    // --- M partial: each thread owns one float4 of the 1024 floats ---
    {
        const float4* K4 = reinterpret_cast<const float4*>(K);
        float4 acc = make_float4(0.f, 0.f, 0.f, 0.f);
#pragma unroll
        for (int ii = 0; ii < I_PER; ii++) {
            const int i = p * I_PER + ii;
            const float w = __ldg(&wlin[i]);
            const float4 kv = K4[i * 256 + tid];
            acc.x = fmaf(w, kv.x, acc.x);
            acc.y = fmaf(w, kv.y, acc.y);
            acc.z = fmaf(w, kv.z, acc.z);
            acc.w = fmaf(w, kv.w, acc.w);
        }
        reinterpret_cast<float4*>(Msm)[tid] = acc;
    }
    __syncthreads();

    // --- C partial: 2 threads per (s,a), each covering half the j range ---
    float c = 0.f;
    if (tid < 2 * S_DIM * A_DIM) {       // 238 active threads
        const int o    = tid >> 1;
        const int half = tid & 1;
        const int s = o / A_DIM;
        const int a = o - s * A_DIM;

        float psi[DPSI];
#pragma unroll
        for (int z = 0; z < DPSI; z++) psi[z] = __ldg(&Wpsi[z * A_DIM + a]);

        const int j0 = half * 64;
#pragma unroll 4
        for (int j = j0; j < j0 + 64; j++) {
            float inner = 0.f;
#pragma unroll
            for (int z = 0; z < DPSI; z++)
                inner = fmaf(Msm[j * DPSI + z], psi[z], inner);
            c = fmaf(__ldg(&Wphi[j * S_DIM + s]), inner, c);
        }
    }
    Ctmp[tid] = c;
    __syncthreads();

    // --- store padded [17][8]; pad column = 0 ---
    if (tid < CPS) {
        const int row = tid >> 3;
        const int col = tid & 7;
        float v = 0.f;
        if (col < A_DIM) {
            const int o = row * A_DIM + col;
            v = Ctmp[2 * o] + Ctmp[2 * o + 1];
        }
        g_Cpart[p * CPS + tid] = v;
    }
}

// ---------------------------------------------------------------------------
// Kernel 2 (R2-proven shape): out[b] = state[b,:] * C * action[b,:]
// 512 blocks x 256 thr, 1 sample/thread. The 32-way partial-C reduce is done
// by 34 threads as float4 register accumulation, ISSUED BEFORE the staging
// LDGs so its L2 latency hides under the DRAM ramp. Single __syncthreads.
// ---------------------------------------------------------------------------
__global__ __launch_bounds__(256)
void k_main(const float* __restrict__ state,   // [B,17]
            const float* __restrict__ action,  // [B,7]
            float* __restrict__ out)           // [B]
{
    __shared__ __align__(16) float Ss[TILE * S_DIM];   // 4352 floats
    __shared__ __align__(16) float As[TILE * A_DIM];   // 1792 floats
    __shared__ __align__(16) float Csm[CPS];           // padded [17][8]

    const int tid = threadIdx.x;
    const int bx  = blockIdx.x;

    // --- partial-C reduce: 34 threads x 32 float4 L2 loads, fixed order ---
    float4 cred = make_float4(0.f, 0.f, 0.f, 0.f);
    if (tid < CPS4) {
        const float4* P4 = reinterpret_cast<const float4*>(g_Cpart);
#pragma unroll 8
        for (int pp = 0; pp < NPART; pp++) {
            const float4 x = P4[pp * CPS4 + tid];
            cred.x += x.x; cred.y += x.y; cred.z += x.z; cred.w += x.w;
        }
    }

    // --- stage state tile: 1088 float4 = 4 full rounds + 64 ---
    {
        const float4* S4 = reinterpret_cast<const float4*>(state) + (size_t)bx * 1088;
        float4* D = reinterpret_cast<float4*>(Ss);
#pragma unroll
        for (int k = 0; k < 4; k++) D[tid + k * 256] = S4[tid + k * 256];
        if (tid < 64) D[tid + 1024] = S4[tid + 1024];
    }
    // --- stage action tile: 448 float4 = 1 full round + 192 ---
    {
        const float4* A4 = reinterpret_cast<const float4*>(action) + (size_t)bx * 448;
        float4* D = reinterpret_cast<float4*>(As);
        D[tid] = A4[tid];
        if (tid < 192) D[tid + 256] = A4[tid + 256];
    }
    // --- park reduced C ---
    if (tid < CPS4) reinterpret_cast<float4*>(Csm)[tid] = cred;

    __syncthreads();   // single barrier

    // --- per-sample bilinear form ---
    const float* av = As + tid * A_DIM;    // lane stride 7: conflict-free
    const float v0 = av[0], v1 = av[1], v2 = av[2], v3 = av[3];
    const float v4 = av[4], v5 = av[5], v6 = av[6];

    const float4* C4 = reinterpret_cast<const float4*>(Csm);
    const float*  st = Ss + tid * S_DIM;   // lane stride 17: conflict-free

    float r = 0.f;
#pragma unroll
    for (int s = 0; s < S_DIM; s++) {
        const float4 c0 = C4[2 * s];       // broadcast LDS.128
        const float4 c1 = C4[2 * s + 1];   // C[s][4..6], pad
        float t;
        t = c0.x * v0;
        t = fmaf(c0.y, v1, t);
        t = fmaf(c0.z, v2, t);
        t = fmaf(c0.w, v3, t);
        t = fmaf(c1.x, v4, t);
        t = fmaf(c1.y, v5, t);
        t = fmaf(c1.z, v6, t);
        r = fmaf(st[s], t, r);
    }

    out[bx * TILE + tid] = r;
}

// ---------------------------------------------------------------------------
extern "C" void kernel_launch(void* const* d_in, const int* in_sizes, int n_in,
                              void* d_out, int out_size)
{
    const float* state  = (const float*)d_in[0];
    const float* action = (const float*)d_in[1];
    const float* Wphi   = (const float*)d_in[2];
    const float* Wpsi   = (const float*)d_in[3];
    const float* K      = (const float*)d_in[4];
    const float* wlin   = (const float*)d_in[5];
    float* out = (float*)d_out;

    k_partialC<<<NPART, 256>>>(Wphi, Wpsi, K, wlin);
    k_main<<<NBLK_MAIN, 256>>>(state, action, out);
}

// round 7
// speedup vs baseline: 1.2851x; 1.0436x over previous
#include <cuda_runtime.h>

// Problem constants (fixed by the dataset)
#define B_TOTAL   131072
#define S_DIM     17
#define A_DIM     7
#define DPHI      128
#define DPSI      8

#define NPART     32                  // blocks in the precompute kernel
#define I_PER     (DPHI / NPART)      // 4 i-values per block
#define CPS       136                 // padded [17][8] floats per partial
#define CPS4      34                  // ... as float4

#define TILE      256                 // samples per k_main block
#define NBLK_MAIN (B_TOTAL / TILE)    // 512 blocks

// Per-block partial C matrices, padded [17][8] (pad col written as 0).
__device__ float g_Cpart[NPART * CPS];

// ---------------------------------------------------------------------------
// Kernel 1 (fence-free): block p computes the partial C over
// i in [p*I_PER, (p+1)*I_PER):
//   M_p[j,z] = sum_{i in chunk} w_lin[i] * K[i,j,z]
//   C_p[s,a] = sum_{j,z} M_p[j,z] * W_phi[j,s] * W_psi[z,a]
// No explicit PDL trigger: the implicit end-of-kernel trigger guarantees all
// g_Cpart writes are visible after cudaGridDependencySynchronize() in k_main.
// ---------------------------------------------------------------------------
__global__ __launch_bounds__(256)
void k_partialC(const float* __restrict__ Wphi,   // [128,17]
                const float* __restrict__ Wpsi,   // [8,7]
                const float* __restrict__ K,      // [128,128,8]
                const float* __restrict__ wlin)   // [1,128]
{
    __shared__ float Msm[DPHI * DPSI];   // 1024 floats, layout j*8+z
    __shared__ float Ctmp[256];

    const int p   = blockIdx.x;
    const int tid = threadIdx.x;         // 256 threads

    // --- M partial: each thread owns one float4 of the 1024 floats ---
    {
        const float4* K4 = reinterpret_cast<const float4*>(K);
        float4 acc = make_float4(0.f, 0.f, 0.f, 0.f);
#pragma unroll
        for (int ii = 0; ii < I_PER; ii++) {
            const int i = p * I_PER + ii;
            const float w = __ldg(&wlin[i]);
            const float4 kv = K4[i * 256 + tid];
            acc.x = fmaf(w, kv.x, acc.x);
            acc.y = fmaf(w, kv.y, acc.y);
            acc.z = fmaf(w, kv.z, acc.z);
            acc.w = fmaf(w, kv.w, acc.w);
        }
        reinterpret_cast<float4*>(Msm)[tid] = acc;
    }
    __syncthreads();

    // --- C partial: 2 threads per (s,a), each covering half the j range ---
    float c = 0.f;
    if (tid < 2 * S_DIM * A_DIM) {       // 238 active threads
        const int o    = tid >> 1;
        const int half = tid & 1;
        const int s = o / A_DIM;
        const int a = o - s * A_DIM;

        float psi[DPSI];
#pragma unroll
        for (int z = 0; z < DPSI; z++) psi[z] = __ldg(&Wpsi[z * A_DIM + a]);

        const int j0 = half * 64;
#pragma unroll 4
        for (int j = j0; j < j0 + 64; j++) {
            float inner = 0.f;
#pragma unroll
            for (int z = 0; z < DPSI; z++)
                inner = fmaf(Msm[j * DPSI + z], psi[z], inner);
            c = fmaf(__ldg(&Wphi[j * S_DIM + s]), inner, c);
        }
    }
    Ctmp[tid] = c;
    __syncthreads();

    // --- store padded [17][8]; pad column = 0 ---
    if (tid < CPS) {
        const int row = tid >> 3;
        const int col = tid & 7;
        float v = 0.f;
        if (col < A_DIM) {
            const int o = row * A_DIM + col;
            v = Ctmp[2 * o] + Ctmp[2 * o + 1];
        }
        g_Cpart[p * CPS + tid] = v;
    }
}

// ---------------------------------------------------------------------------
// Kernel 2 (PDL secondary): out[b] = state[b,:] * C * action[b,:]
// Launched with programmatic stream serialization: the launch and the 13 MB
// staging burst overlap k_partialC's execution; cudaGridDependencySynchronize
// gates only the g_Cpart reads.
// ---------------------------------------------------------------------------
__global__ __launch_bounds__(256)
void k_main(const float* __restrict__ state,   // [B,17]
            const float* __restrict__ action,  // [B,7]
            float* __restrict__ out)           // [B]
{
    __shared__ __align__(16) float Ss[TILE * S_DIM];   // 4352 floats
    __shared__ __align__(16) float As[TILE * A_DIM];   // 1792 floats
    __shared__ __align__(16) float Csm[CPS];           // padded [17][8]

    const int tid = threadIdx.x;
    const int bx  = blockIdx.x;

    // --- stage state tile: 1088 float4 = 4 full rounds + 64 (MLP ~5) ---
    {
        const float4* S4 = reinterpret_cast<const float4*>(state) + (size_t)bx * 1088;
        float4* D = reinterpret_cast<float4*>(Ss);
#pragma unroll
        for (int k = 0; k < 4; k++) D[tid + k * 256] = S4[tid + k * 256];
        if (tid < 64) D[tid + 1024] = S4[tid + 1024];
    }
    // --- stage action tile: 448 float4 = 1 full round + 192 ---
    {
        const float4* A4 = reinterpret_cast<const float4*>(action) + (size_t)bx * 448;
        float4* D = reinterpret_cast<float4*>(As);
        D[tid] = A4[tid];
        if (tid < 192) D[tid + 256] = A4[tid + 256];
    }

    // --- wait for k_partialC completion (overlaps the staging above) ---
    cudaGridDependencySynchronize();

    // --- partial-C reduce: 34 threads x 32 float4 L2 loads, fixed order ---
    if (tid < CPS4) {
        const float4* P4 = reinterpret_cast<const float4*>(g_Cpart);
        float4 cred = make_float4(0.f, 0.f, 0.f, 0.f);
#pragma unroll 8
        for (int pp = 0; pp < NPART; pp++) {
            const float4 x = P4[pp * CPS4 + tid];
            cred.x += x.x; cred.y += x.y; cred.z += x.z; cred.w += x.w;
        }
        reinterpret_cast<float4*>(Csm)[tid] = cred;
    }

    __syncthreads();

    // --- per-sample bilinear form ---
    const float* av = As + tid * A_DIM;    // lane stride 7: conflict-free
    const float v0 = av[0], v1 = av[1], v2 = av[2], v3 = av[3];
    const float v4 = av[4], v5 = av[5], v6 = av[6];

    const float4* C4 = reinterpret_cast<const float4*>(Csm);
    const float*  st = Ss + tid * S_DIM;   // lane stride 17: conflict-free

    float r = 0.f;
#pragma unroll
    for (int s = 0; s < S_DIM; s++) {
        const float4 c0 = C4[2 * s];       // broadcast LDS.128
        const float4 c1 = C4[2 * s + 1];   // C[s][4..6], pad
        float t;
        t = c0.x * v0;
        t = fmaf(c0.y, v1, t);
        t = fmaf(c0.z, v2, t);
        t = fmaf(c0.w, v3, t);
        t = fmaf(c1.x, v4, t);
        t = fmaf(c1.y, v5, t);
        t = fmaf(c1.z, v6, t);
        r = fmaf(st[s], t, r);
    }

    out[bx * TILE + tid] = r;
}

// ---------------------------------------------------------------------------
extern "C" void kernel_launch(void* const* d_in, const int* in_sizes, int n_in,
                              void* d_out, int out_size)
{
    const float* state  = (const float*)d_in[0];
    const float* action = (const float*)d_in[1];
    const float* Wphi   = (const float*)d_in[2];
    const float* Wpsi   = (const float*)d_in[3];
    const float* K      = (const float*)d_in[4];
    const float* wlin   = (const float*)d_in[5];
    float* out = (float*)d_out;

    k_partialC<<<NPART, 256>>>(Wphi, Wpsi, K, wlin);

    // PDL secondary launch: overlap with k_partialC.
    cudaLaunchConfig_t cfg = {};
    cfg.gridDim  = dim3(NBLK_MAIN, 1, 1);
    cfg.blockDim = dim3(256, 1, 1);
    cfg.dynamicSmemBytes = 0;
    cfg.stream = 0;
    cudaLaunchAttribute attr[1];
    attr[0].id = cudaLaunchAttributeProgrammaticStreamSerialization;
    attr[0].val.programmaticStreamSerializationAllowed = 1;
    cfg.attrs    = attr;
    cfg.numAttrs = 1;
    cudaLaunchKernelEx(&cfg, k_main, state, action, out);
}

// round 8
// speedup vs baseline: 1.3549x; 1.0543x over previous
#include <cuda_runtime.h>
#include <cstdint>

// Problem constants (fixed by the dataset)
#define B_TOTAL   131072
#define S_DIM     17
#define A_DIM     7
#define DPHI      128
#define DPSI      8

#define NPART     32                  // blocks in the precompute kernel
#define I_PER     (DPHI / NPART)      // 4 i-values per block
#define CPS       136                 // padded [17][8] floats per partial
#define CPS4      34                  // ... as float4

#define TILE      256                 // samples per k_main block
#define NBLK_MAIN (B_TOTAL / TILE)    // 512 blocks

// Per-block partial C matrices, padded [17][8] (pad col written as 0).
__device__ float g_Cpart[NPART * CPS];

// 16-byte async copy global->shared, fire-and-forget (no scoreboard block).
__device__ __forceinline__ void cp16(uint32_t dst_smem, const void* src) {
    asm volatile("cp.async.cg.shared.global [%0], [%1], 16;"
                 :: "r"(dst_smem), "l"(src) : "memory");
}
__device__ __forceinline__ void cp_async_wait_all() {
    asm volatile("cp.async.wait_all;" ::: "memory");
}

// ---------------------------------------------------------------------------
// Kernel 1 (fence-free): block p computes the partial C over
// i in [p*I_PER, (p+1)*I_PER):
//   M_p[j,z] = sum_{i in chunk} w_lin[i] * K[i,j,z]
//   C_p[s,a] = sum_{j,z} M_p[j,z] * W_phi[j,s] * W_psi[z,a]
// Implicit PDL completion trigger covers the g_Cpart writes.
// ---------------------------------------------------------------------------
__global__ __launch_bounds__(256)
void k_partialC(const float* __restrict__ Wphi,   // [128,17]
                const float* __restrict__ Wpsi,   // [8,7]
                const float* __restrict__ K,      // [128,128,8]
                const float* __restrict__ wlin)   // [1,128]
{
    __shared__ float Msm[DPHI * DPSI];   // 1024 floats, layout j*8+z
    __shared__ float Ctmp[256];

    const int p   = blockIdx.x;
    const int tid = threadIdx.x;         // 256 threads

    // --- M partial: each thread owns one float4 of the 1024 floats ---
    {
        const float4* K4 = reinterpret_cast<const float4*>(K);
        float4 acc = make_float4(0.f, 0.f, 0.f, 0.f);
#pragma unroll
        for (int ii = 0; ii < I_PER; ii++) {
            const int i = p * I_PER + ii;
            const float w = __ldg(&wlin[i]);
            const float4 kv = K4[i * 256 + tid];
            acc.x = fmaf(w, kv.x, acc.x);
            acc.y = fmaf(w, kv.y, acc.y);
            acc.z = fmaf(w, kv.z, acc.z);
            acc.w = fmaf(w, kv.w, acc.w);
        }
        reinterpret_cast<float4*>(Msm)[tid] = acc;
    }
    __syncthreads();

    // --- C partial: 2 threads per (s,a), each covering half the j range ---
    float c = 0.f;
    if (tid < 2 * S_DIM * A_DIM) {       // 238 active threads
        const int o    = tid >> 1;
        const int half = tid & 1;
        const int s = o / A_DIM;
        const int a = o - s * A_DIM;

        float psi[DPSI];
#pragma unroll
        for (int z = 0; z < DPSI; z++) psi[z] = __ldg(&Wpsi[z * A_DIM + a]);

        const int j0 = half * 64;
#pragma unroll 4
        for (int j = j0; j < j0 + 64; j++) {
            float inner = 0.f;
#pragma unroll
            for (int z = 0; z < DPSI; z++)
                inner = fmaf(Msm[j * DPSI + z], psi[z], inner);
            c = fmaf(__ldg(&Wphi[j * S_DIM + s]), inner, c);
        }
    }
    Ctmp[tid] = c;
    __syncthreads();

    // --- store padded [17][8]; pad column = 0 ---
    if (tid < CPS) {
        const int row = tid >> 3;
        const int col = tid & 7;
        float v = 0.f;
        if (col < A_DIM) {
            const int o = row * A_DIM + col;
            v = Ctmp[2 * o] + Ctmp[2 * o + 1];
        }
        g_Cpart[p * CPS + tid] = v;
    }
}

// ---------------------------------------------------------------------------
// Kernel 2 (PDL secondary): out[b] = state[b,:] * C * action[b,:]
// Staging via cp.async (LDGSTS): all 7 16B copies per thread are issued
// back-to-back with no scoreboard dependency -> full bytes-in-flight.
// ---------------------------------------------------------------------------
__global__ __launch_bounds__(256)
void k_main(const float* __restrict__ state,   // [B,17]
            const float* __restrict__ action,  // [B,7]
            float* __restrict__ out)           // [B]
{
    __shared__ __align__(16) float Ss[TILE * S_DIM];   // 4352 floats
    __shared__ __align__(16) float As[TILE * A_DIM];   // 1792 floats
    __shared__ __align__(16) float Csm[CPS];           // padded [17][8]

    const int tid = threadIdx.x;
    const int bx  = blockIdx.x;

    // --- issue ALL staging copies asynchronously (no blocking) ---
    {
        const float4* S4 = reinterpret_cast<const float4*>(state)  + (size_t)bx * 1088;
        const float4* A4 = reinterpret_cast<const float4*>(action) + (size_t)bx * 448;
        uint32_t Ds = (uint32_t)__cvta_generic_to_shared(Ss);
        uint32_t Da = (uint32_t)__cvta_generic_to_shared(As);
#pragma unroll
        for (int k = 0; k < 4; k++)
            cp16(Ds + (tid + k * 256) * 16, S4 + tid + k * 256);
        if (tid < 64)
            cp16(Ds + (tid + 1024) * 16, S4 + tid + 1024);
        cp16(Da + tid * 16, A4 + tid);
        if (tid < 192)
            cp16(Da + (tid + 256) * 16, A4 + tid + 256);
    }

    // --- wait for k_partialC completion (overlaps the copies above) ---
    cudaGridDependencySynchronize();

    // --- partial-C reduce: 34 threads x 32 float4 L2 loads, fixed order ---
    if (tid < CPS4) {
        const float4* P4 = reinterpret_cast<const float4*>(g_Cpart);
        float4 cred = make_float4(0.f, 0.f, 0.f, 0.f);
#pragma unroll 8
        for (int pp = 0; pp < NPART; pp++) {
            const float4 x = P4[pp * CPS4 + tid];
            cred.x += x.x; cred.y += x.y; cred.z += x.z; cred.w += x.w;
        }
        reinterpret_cast<float4*>(Csm)[tid] = cred;
    }

    cp_async_wait_all();
    __syncthreads();

    // --- per-sample bilinear form ---
    const float* av = As + tid * A_DIM;    // lane stride 7: conflict-free
    const float v0 = av[0], v1 = av[1], v2 = av[2], v3 = av[3];
    const float v4 = av[4], v5 = av[5], v6 = av[6];

    const float4* C4 = reinterpret_cast<const float4*>(Csm);
    const float*  st = Ss + tid * S_DIM;   // lane stride 17: conflict-free

    float r = 0.f;
#pragma unroll
    for (int s = 0; s < S_DIM; s++) {
        const float4 c0 = C4[2 * s];       // broadcast LDS.128
        const float4 c1 = C4[2 * s + 1];   // C[s][4..6], pad
        float t;
        t = c0.x * v0;
        t = fmaf(c0.y, v1, t);
        t = fmaf(c0.z, v2, t);
        t = fmaf(c0.w, v3, t);
        t = fmaf(c1.x, v4, t);
        t = fmaf(c1.y, v5, t);
        t = fmaf(c1.z, v6, t);
        r = fmaf(st[s], t, r);
    }

    out[bx * TILE + tid] = r;
}

// ---------------------------------------------------------------------------
extern "C" void kernel_launch(void* const* d_in, const int* in_sizes, int n_in,
                              void* d_out, int out_size)
{
    const float* state  = (const float*)d_in[0];
    const float* action = (const float*)d_in[1];
    const float* Wphi   = (const float*)d_in[2];
    const float* Wpsi   = (const float*)d_in[3];
    const float* K      = (const float*)d_in[4];
    const float* wlin   = (const float*)d_in[5];
    float* out = (float*)d_out;

    k_partialC<<<NPART, 256>>>(Wphi, Wpsi, K, wlin);

    // PDL secondary launch: overlap with k_partialC.
    cudaLaunchConfig_t cfg = {};
    cfg.gridDim  = dim3(NBLK_MAIN, 1, 1);
    cfg.blockDim = dim3(256, 1, 1);
    cfg.dynamicSmemBytes = 0;
    cfg.stream = 0;
    cudaLaunchAttribute attr[1];
    attr[0].id = cudaLaunchAttributeProgrammaticStreamSerialization;
    attr[0].val.programmaticStreamSerializationAllowed = 1;
    cfg.attrs    = attr;
    cfg.numAttrs = 1;
    cudaLaunchKernelEx(&cfg, k_main, state, action, out);
}